// round 3
// baseline (speedup 1.0000x reference)
#include <cuda_runtime.h>

// Problem constants
#define BB 16
#define CC 256
#define HH 64
#define WW 64
#define EE 4
#define K9 9
#define EPS_BN 1e-5f

// Conv tiling
#define TC 32   // output channels per block
#define TP 16   // spatial tile (TP x TP outputs)
#define CK 8    // input-channel chunk staged in smem

// Scratch (no cudaMalloc allowed -> __device__ globals)
__device__ float g_y[(size_t)BB*CC*HH*WW];        // post cv1 activation  (64 MB)
__device__ float g_kern[(size_t)BB*CC*CC*K9];     // per-sample conv2 weights (37.7 MB)
__device__ float g_pool[BB*CC];
__device__ float g_rout[BB*EE];

// packed f32x2 helpers (SASS FFMA2 — ptxas never emits this from C++)
__device__ __forceinline__ unsigned long long pack2(float v) {
    unsigned long long r;
    asm("mov.b64 %0, {%1, %1};" : "=l"(r) : "r"(__float_as_uint(v)));
    return r;
}
__device__ __forceinline__ void fma2(unsigned long long& acc,
                                     unsigned long long a, unsigned long long b) {
    asm("fma.rn.f32x2 %0, %1, %2, %0;" : "+l"(acc) : "l"(a), "l"(b));
}

// ---------------------------------------------------------------------------
// Fused 3x3 conv (stride 1, pad 1) + BN(eval) + SiLU (+ optional residual)
// grid: (16 spatial tiles, CC/TC, BB), block: 256 threads
// Each thread: 2x2 output pixels x 8 output channels = 16 packed accumulators.
// ---------------------------------------------------------------------------
template<bool PER_SAMPLE, bool RESID>
__global__ __launch_bounds__(256)
void conv3x3_fused(const float* __restrict__ in,   // [B,C,H,W]
                   const float* __restrict__ wt,   // [C,C,3,3] or [B,C,C,3,3]
                   const float* __restrict__ bg,
                   const float* __restrict__ bb,
                   const float* __restrict__ bm,
                   const float* __restrict__ bv,
                   const float* __restrict__ resid,
                   float* __restrict__ out)
{
    __shared__ float s_in[CK][18][20];   // halo tile, padded row stride
    __shared__ float s_w[CK][K9][TC];    // weights, cout contiguous

    const int tid  = threadIdx.x;
    const int b    = blockIdx.z;
    const int co0  = blockIdx.y * TC;
    const int tile = blockIdx.x;              // 0..15 -> 4x4 tile grid
    const int ty0  = (tile >> 2) * TP;
    const int tx0  = (tile & 3) * TP;

    const int cg  = tid >> 6;                 // 0..3 (8 couts each)
    const int pix = tid & 63;
    const int py  = (pix >> 3) << 1;          // 0..14 even
    const int px  = (pix & 7) << 1;

    const float* wbase = wt + (PER_SAMPLE ? (size_t)b * CC * CC * K9 : 0);

    // acc2[dy][dx][p] packs couts (2p, 2p+1) for pixel (py+dy, px+dx)
    unsigned long long acc2[2][2][4];
    #pragma unroll
    for (int i = 0; i < 2; i++)
        #pragma unroll
        for (int j = 0; j < 2; j++)
            #pragma unroll
            for (int p = 0; p < 4; p++) acc2[i][j][p] = 0ull;

    for (int ci0 = 0; ci0 < CC; ci0 += CK) {
        __syncthreads();   // protect previous chunk's smem reads

        // stage input halo: CK x 18 x 18
        for (int i = tid; i < CK * 18 * 18; i += 256) {
            int ck = i / 324;
            int r  = (i - ck * 324) / 18;
            int c  = i - ck * 324 - r * 18;
            int gy = ty0 + r - 1;
            int gx = tx0 + c - 1;
            float v = 0.f;
            if ((unsigned)gy < (unsigned)HH && (unsigned)gx < (unsigned)WW)
                v = in[(((size_t)b * CC + (ci0 + ck)) * HH + gy) * WW + gx];
            s_in[ck][r][c] = v;
        }
        // stage weights: s_w[ck][k][co]
        for (int i = tid; i < CK * K9 * TC; i += 256) {
            int co  = i / (CK * K9);
            int rem = i - co * (CK * K9);
            int ck  = rem / K9;
            int k   = rem - ck * K9;
            s_w[ck][k][co] = wbase[((size_t)(co0 + co) * CC + (ci0 + ck)) * K9 + k];
        }
        __syncthreads();

        #pragma unroll 1
        for (int ck = 0; ck < CK; ck++) {
            float win[4][4];
            #pragma unroll
            for (int r = 0; r < 4; r++)
                #pragma unroll
                for (int c = 0; c < 4; c++)
                    win[r][c] = s_in[ck][py + r][px + c];

            #pragma unroll
            for (int k = 0; k < K9; k++) {
                const int kh = k / 3, kw = k % 3;
                // 8 couts = 4 packed pairs, 64-bit loads from smem (cg uniform per warp)
                const unsigned long long* wp =
                    reinterpret_cast<const unsigned long long*>(&s_w[ck][k][cg << 3]);
                unsigned long long w0 = wp[0], w1 = wp[1], w2 = wp[2], w3 = wp[3];
                #pragma unroll
                for (int dy = 0; dy < 2; dy++)
                    #pragma unroll
                    for (int dx = 0; dx < 2; dx++) {
                        unsigned long long vv = pack2(win[dy + kh][dx + kw]);
                        fma2(acc2[dy][dx][0], vv, w0);
                        fma2(acc2[dy][dx][1], vv, w1);
                        fma2(acc2[dy][dx][2], vv, w2);
                        fma2(acc2[dy][dx][3], vv, w3);
                    }
            }
        }
    }

    // epilogue: BN + SiLU (+ residual)
    #pragma unroll
    for (int p = 0; p < 4; p++) {
        #pragma unroll
        for (int half = 0; half < 2; half++) {
            int j  = (p << 1) + half;
            int co = co0 + (cg << 3) + j;
            float scale = bg[co] * rsqrtf(bv[co] + EPS_BN);
            float shift = bb[co] - bm[co] * scale;
            #pragma unroll
            for (int dy = 0; dy < 2; dy++)
                #pragma unroll
                for (int dx = 0; dx < 2; dx++) {
                    float lo, hi;
                    asm("mov.b64 {%0, %1}, %2;"
                        : "=f"(lo), "=f"(hi) : "l"(acc2[dy][dx][p]));
                    float a = half ? hi : lo;
                    int oy = ty0 + py + dy, ox = tx0 + px + dx;
                    size_t oidx = (((size_t)b * CC + co) * HH + oy) * WW + ox;
                    float t = a * scale + shift;
                    float v = t / (1.f + __expf(-t));      // SiLU
                    if (RESID) v += resid[oidx];
                    out[oidx] = v;
                }
        }
    }
}

// ---------------------------------------------------------------------------
// Global average pool: one block per (b,c)
// ---------------------------------------------------------------------------
__global__ void pool_kernel(const float* __restrict__ y, float* __restrict__ pool)
{
    int bc = blockIdx.x;
    const float* p = y + (size_t)bc * HH * WW;
    float s = 0.f;
    for (int i = threadIdx.x; i < HH * WW; i += 256) s += p[i];
    __shared__ float sm[256];
    sm[threadIdx.x] = s;
    __syncthreads();
    for (int st = 128; st > 0; st >>= 1) {
        if (threadIdx.x < st) sm[threadIdx.x] += sm[threadIdx.x + st];
        __syncthreads();
    }
    if (threadIdx.x == 0) pool[bc] = sm[0] * (1.f / (HH * WW));
}

// ---------------------------------------------------------------------------
// Routing: sigmoid(pooled @ wr.T + br)  -> [B,E]
// ---------------------------------------------------------------------------
__global__ void routing_kernel(const float* __restrict__ pool,
                               const float* __restrict__ wr,
                               const float* __restrict__ br,
                               float* __restrict__ rout)
{
    int t = threadIdx.x;
    if (t >= BB * EE) return;
    int b = t / EE, e = t - b * EE;
    float s = br[e];
    for (int c = 0; c < CC; c++) s += pool[b * CC + c] * wr[e * CC + c];
    rout[t] = 1.f / (1.f + __expf(-s));
}

// ---------------------------------------------------------------------------
// Per-sample kernel bank: kern[b, :] = sum_e rout[b,e] * w_e[e, :]
// ---------------------------------------------------------------------------
__global__ void kern_kernel(const float* __restrict__ rout,
                            const float* __restrict__ we,
                            float* __restrict__ kern)
{
    const int CC94 = CC * CC * K9 / 4;     // 147456 float4 per sample
    const int N4   = BB * CC94;
    const float4* we4 = reinterpret_cast<const float4*>(we);
    float4* k4 = reinterpret_cast<float4*>(kern);
    for (int i = blockIdx.x * blockDim.x + threadIdx.x; i < N4;
         i += gridDim.x * blockDim.x) {
        int b = i / CC94;
        int j = i - b * CC94;
        float r0 = rout[b * EE + 0], r1 = rout[b * EE + 1];
        float r2 = rout[b * EE + 2], r3 = rout[b * EE + 3];
        float4 a0 = we4[0 * CC94 + j], a1 = we4[1 * CC94 + j];
        float4 a2 = we4[2 * CC94 + j], a3 = we4[3 * CC94 + j];
        float4 o;
        o.x = r0 * a0.x + r1 * a1.x + r2 * a2.x + r3 * a3.x;
        o.y = r0 * a0.y + r1 * a1.y + r2 * a2.y + r3 * a3.y;
        o.z = r0 * a0.z + r1 * a1.z + r2 * a2.z + r3 * a3.z;
        o.w = r0 * a0.w + r1 * a1.w + r2 * a2.w + r3 * a3.w;
        k4[i] = o;
    }
}

// ---------------------------------------------------------------------------
extern "C" void kernel_launch(void* const* d_in, const int* in_sizes, int n_in,
                              void* d_out, int out_size)
{
    (void)in_sizes; (void)n_in; (void)out_size;
    const float* x   = (const float*)d_in[0];
    const float* w1  = (const float*)d_in[1];
    const float* b1g = (const float*)d_in[2];
    const float* b1b = (const float*)d_in[3];
    const float* b1m = (const float*)d_in[4];
    const float* b1v = (const float*)d_in[5];
    const float* wr  = (const float*)d_in[6];
    const float* br  = (const float*)d_in[7];
    const float* we  = (const float*)d_in[8];
    const float* b2g = (const float*)d_in[9];
    const float* b2b = (const float*)d_in[10];
    const float* b2m = (const float*)d_in[11];
    const float* b2v = (const float*)d_in[12];
    float* out = (float*)d_out;

    float *y, *kern, *pool, *rout;
    cudaGetSymbolAddress((void**)&y,    g_y);
    cudaGetSymbolAddress((void**)&kern, g_kern);
    cudaGetSymbolAddress((void**)&pool, g_pool);
    cudaGetSymbolAddress((void**)&rout, g_rout);

    dim3 grid(16, CC / TC, BB);   // (spatial tiles, cout tiles, batch)

    // cv1: conv + BN1 + SiLU -> y
    conv3x3_fused<false, false><<<grid, 256>>>(x, w1, b1g, b1b, b1m, b1v,
                                               nullptr, y);
    // routing path
    pool_kernel<<<BB * CC, 256>>>(y, pool);
    routing_kernel<<<1, 64>>>(pool, wr, br, rout);
    kern_kernel<<<4608, 256>>>(rout, we, kern);
    // cv2: per-sample conv + BN2 + SiLU + residual(x) -> out
    conv3x3_fused<true, true><<<grid, 256>>>(y, kern, b2g, b2b, b2m, b2v,
                                             x, out);
}

// round 4
// speedup vs baseline: 1.0495x; 1.0495x over previous
#include <cuda_runtime.h>
#include <cuda_bf16.h>
#include <cstdint>

// Problem constants
#define BB 16
#define CC 256
#define HH 64
#define WW 64
#define EE 4
#define K9 9
#define EPS_BN 1e-5f
#define KC 32      // K chunk (input channels per stage)

// Scratch (no cudaMalloc allowed -> __device__ globals)
__device__ float g_y[(size_t)BB*CC*HH*WW];       // post cv1 activation (64 MB)
__device__ float g_w1r[(size_t)K9*CC*CC];        // w1 reordered [k][cout][ci]
__device__ float g_k2[(size_t)BB*K9*CC*CC];      // per-sample conv2 weights [b][k][cout][ci]
__device__ float g_pool[BB*CC];
__device__ float g_rout[BB*EE];

// ---------------------------------------------------------------------------
// helpers
// ---------------------------------------------------------------------------
__device__ __forceinline__ unsigned sw(unsigned off) {      // 128B XOR swizzle
    return off ^ ((off >> 3) & 0x70u);
}

__device__ __forceinline__ void bsplit(float v, unsigned short& h, unsigned short& l) {
    __nv_bfloat16 bh = __float2bfloat16(v);
    float rres = v - __bfloat162float(bh);
    __nv_bfloat16 bl = __float2bfloat16(rres);
    h = reinterpret_cast<unsigned short&>(bh);
    l = reinterpret_cast<unsigned short&>(bl);
}

__device__ __forceinline__ void ldm_x4(unsigned& a0, unsigned& a1, unsigned& a2,
                                       unsigned& a3, unsigned addr) {
    asm volatile("ldmatrix.sync.aligned.m8n8.x4.shared.b16 {%0,%1,%2,%3}, [%4];"
                 : "=r"(a0), "=r"(a1), "=r"(a2), "=r"(a3) : "r"(addr));
}
__device__ __forceinline__ void ldm_x2t(unsigned& b0, unsigned& b1, unsigned addr) {
    asm volatile("ldmatrix.sync.aligned.m8n8.x2.trans.shared.b16 {%0,%1}, [%2];"
                 : "=r"(b0), "=r"(b1) : "r"(addr));
}
__device__ __forceinline__ void mma16816(float* c, const unsigned* a, const unsigned* b) {
    asm volatile("mma.sync.aligned.m16n8k16.row.col.f32.bf16.bf16.f32 "
                 "{%0,%1,%2,%3}, {%4,%5,%6,%7}, {%8,%9}, {%0,%1,%2,%3};"
                 : "+f"(c[0]), "+f"(c[1]), "+f"(c[2]), "+f"(c[3])
                 : "r"(a[0]), "r"(a[1]), "r"(a[2]), "r"(a[3]),
                   "r"(b[0]), "r"(b[1]));
}

// ---------------------------------------------------------------------------
// Implicit-GEMM 3x3 conv (pad 1) via mma.sync bf16 with hi/lo split (3 products)
// CTA: 128 couts x 128 pixels (2 image rows). 8 warps: 2(M) x 4(N), warp 64x32.
// grid: (512 pixel tiles, 2 cout tiles)
// smem 32KB: A [128 rows x 128B] (hi bytes 0-63 | lo 64-127),
//            B hi [2 halves][32k x 64px], B lo same, each row 128B.
// ---------------------------------------------------------------------------
template<bool PER_SAMPLE, bool RESID>
__global__ __launch_bounds__(256)
void conv_mma(const float* __restrict__ src,   // [B,C,H,W] fp32 activations
              const float* __restrict__ A,     // [(b)][9][C][C] fp32 weights
              const float* __restrict__ bg, const float* __restrict__ bb,
              const float* __restrict__ bm, const float* __restrict__ bv,
              const float* __restrict__ resid,
              float* __restrict__ out)
{
    __shared__ __align__(1024) unsigned char smm[32768];
    const unsigned sb = (unsigned)__cvta_generic_to_shared(smm);
    // byte regions: A: [0,16384)  Bh: [16384,24576)  Bl: [24576,32768)

    const int tid = threadIdx.x, lane = tid & 31, w = tid >> 5;
    const int warp_m = w & 1, warp_n = w >> 1;
    const int pt = blockIdx.x;
    const int b  = pt >> 5;
    const int y0 = (pt & 31) << 1;
    const int cout0 = blockIdx.y << 7;

    const float* Ab = A + (PER_SAMPLE ? (size_t)b * K9 * CC * CC : 0);

    float c[4][4][4];
    #pragma unroll
    for (int i = 0; i < 4; i++)
        #pragma unroll
        for (int j = 0; j < 4; j++)
            #pragma unroll
            for (int k = 0; k < 4; k++) c[i][j][k] = 0.f;

    for (int k9 = 0; k9 < K9; k9++) {
        const int ky = k9 / 3 - 1, kx = k9 % 3 - 1;
        for (int ci0 = 0; ci0 < CC; ci0 += KC) {
            __syncthreads();   // previous chunk fully consumed

            // ---- stage A: 128 cout x 32 ci fp32 -> split bf16 hi/lo ----
            {
                const float* Asrc = Ab + ((size_t)k9 * CC + cout0) * CC + ci0;
                #pragma unroll
                for (int j = 0; j < 8; j++) {
                    int pidx = tid + j * 256;          // 2048 float2 pairs
                    int m = pidx >> 4, cp = pidx & 15; // cp = ci pair index
                    float2 v = *reinterpret_cast<const float2*>(Asrc + m * CC + cp * 2);
                    unsigned short h0, l0, h1, l1;
                    bsplit(v.x, h0, l0);
                    bsplit(v.y, h1, l1);
                    unsigned hp = (unsigned)h0 | ((unsigned)h1 << 16);
                    unsigned lp = (unsigned)l0 | ((unsigned)l1 << 16);
                    unsigned off = (unsigned)(m * 128 + cp * 4);
                    *reinterpret_cast<unsigned*>(smm + sw(off))      = hp;
                    *reinterpret_cast<unsigned*>(smm + sw(off + 64)) = lp;
                }
            }
            // ---- stage B: 32 ci x 128 px (shifted, zero-padded) ----
            {
                #pragma unroll
                for (int j = 0; j < 8; j++) {
                    int pidx = tid + j * 256;          // 2048 px pairs
                    int k  = pidx >> 6;                // ci local
                    int pp = pidx & 63;                // px pair
                    int px0 = pp * 2;                  // 0..126 even
                    int hh  = px0 >> 6;                // image row within tile
                    int pxl = px0 & 63;                // x coordinate (even)
                    int ys  = y0 + hh + ky;
                    float v0 = 0.f, v1 = 0.f;
                    if ((unsigned)ys < (unsigned)HH) {
                        const float* row = src +
                            (((size_t)b * CC + ci0 + k) * HH + ys) * WW;
                        int xs = pxl + kx;
                        if ((unsigned)xs       < (unsigned)WW) v0 = row[xs];
                        if ((unsigned)(xs + 1) < (unsigned)WW) v1 = row[xs + 1];
                    }
                    unsigned short h0, l0, h1, l1;
                    bsplit(v0, h0, l0);
                    bsplit(v1, h1, l1);
                    unsigned hp = (unsigned)h0 | ((unsigned)h1 << 16);
                    unsigned lp = (unsigned)l0 | ((unsigned)l1 << 16);
                    unsigned off = sw((unsigned)(k * 128 + pxl * 2));
                    *reinterpret_cast<unsigned*>(smm + 16384 + hh * 4096 + off) = hp;
                    *reinterpret_cast<unsigned*>(smm + 24576 + hh * 4096 + off) = lp;
                }
            }
            __syncthreads();

            // ---- compute: 2 k-steps of 16 ----
            #pragma unroll
            for (int ks = 0; ks < 2; ks++) {
                unsigned bhf[4][2], blf[4][2];
                const int l2 = lane & 15;
                #pragma unroll
                for (int ni = 0; ni < 4; ni++) {
                    int noff = warp_n * 32 + ni * 8;
                    int hh = noff >> 6, nn = noff & 63;
                    unsigned loc = sw((unsigned)((ks * 16 + l2) * 128 + nn * 2));
                    ldm_x2t(bhf[ni][0], bhf[ni][1], sb + 16384 + hh * 4096 + loc);
                    ldm_x2t(blf[ni][0], blf[ni][1], sb + 24576 + hh * 4096 + loc);
                }
                #pragma unroll
                for (int mi = 0; mi < 4; mi++) {
                    int m = warp_m * 64 + mi * 16 + (lane & 15);
                    unsigned kb = (unsigned)(ks * 32 + ((lane >> 4) << 4));
                    unsigned ah[4], al[4];
                    ldm_x4(ah[0], ah[1], ah[2], ah[3], sb + sw((unsigned)(m * 128) + kb));
                    ldm_x4(al[0], al[1], al[2], al[3], sb + sw((unsigned)(m * 128) + 64u + kb));
                    #pragma unroll
                    for (int ni = 0; ni < 4; ni++) {
                        mma16816(c[mi][ni], ah, bhf[ni]);
                        mma16816(c[mi][ni], ah, blf[ni]);
                        mma16816(c[mi][ni], al, bhf[ni]);
                    }
                }
            }
        }
    }

    // ---- epilogue: BN + SiLU (+ residual), float2 stores ----
    const int q = lane & 3, r = lane >> 2;
    #pragma unroll
    for (int mi = 0; mi < 4; mi++) {
        #pragma unroll
        for (int rr = 0; rr < 2; rr++) {
            int cout = cout0 + warp_m * 64 + mi * 16 + r + rr * 8;
            float scale = bg[cout] * rsqrtf(bv[cout] + EPS_BN);
            float shift = bb[cout] - bm[cout] * scale;
            #pragma unroll
            for (int ni = 0; ni < 4; ni++) {
                int pix = warp_n * 32 + ni * 8 + q * 2;
                int yy = y0 + (pix >> 6), xx = pix & 63;
                size_t oidx = (((size_t)b * CC + cout) * HH + yy) * WW + xx;
                float t0 = c[mi][ni][rr * 2 + 0] * scale + shift;
                float t1 = c[mi][ni][rr * 2 + 1] * scale + shift;
                float o0 = t0 / (1.f + __expf(-t0));
                float o1 = t1 / (1.f + __expf(-t1));
                if (RESID) {
                    float2 rv = *reinterpret_cast<const float2*>(resid + oidx);
                    o0 += rv.x; o1 += rv.y;
                }
                float2 ov = {o0, o1};
                *reinterpret_cast<float2*>(out + oidx) = ov;
            }
        }
    }
}

// ---------------------------------------------------------------------------
// w1 reorder: [cout][ci][k] -> [k][cout][ci]
// ---------------------------------------------------------------------------
__global__ void w1_prep(const float* __restrict__ w1, float* __restrict__ outw)
{
    __shared__ float s[K9][CC];
    int cout = blockIdx.x, ci = threadIdx.x;
    const float* p = w1 + ((size_t)cout * CC + ci) * K9;
    #pragma unroll
    for (int k = 0; k < K9; k++) s[k][ci] = p[k];
    __syncthreads();
    for (int i = ci; i < K9 * CC; i += 256) {
        int k = i >> 8, c2 = i & 255;
        outw[((size_t)k * CC + cout) * CC + c2] = s[k][c2];
    }
}

// ---------------------------------------------------------------------------
// kern prep (fused expert mix + reorder): out[b][k][cout][ci]
// ---------------------------------------------------------------------------
__global__ void kern_prep(const float* __restrict__ rout,
                          const float* __restrict__ we,
                          float* __restrict__ outw)
{
    __shared__ float s[K9][CC];
    int cout = blockIdx.x, b = blockIdx.y, ci = threadIdx.x;
    float r0 = rout[b * EE + 0], r1 = rout[b * EE + 1];
    float r2 = rout[b * EE + 2], r3 = rout[b * EE + 3];
    const size_t es = (size_t)CC * CC * K9;
    const float* p = we + ((size_t)cout * CC + ci) * K9;
    #pragma unroll
    for (int k = 0; k < K9; k++)
        s[k][ci] = r0 * p[k] + r1 * p[es + k] + r2 * p[2 * es + k] + r3 * p[3 * es + k];
    __syncthreads();
    for (int i = ci; i < K9 * CC; i += 256) {
        int k = i >> 8, c2 = i & 255;
        outw[(((size_t)b * K9 + k) * CC + cout) * CC + c2] = s[k][c2];
    }
}

// ---------------------------------------------------------------------------
// Global average pool: one block per (b,c)
// ---------------------------------------------------------------------------
__global__ void pool_kernel(const float* __restrict__ y, float* __restrict__ pool)
{
    int bc = blockIdx.x;
    const float* p = y + (size_t)bc * HH * WW;
    float s = 0.f;
    for (int i = threadIdx.x; i < HH * WW; i += 256) s += p[i];
    __shared__ float sm[256];
    sm[threadIdx.x] = s;
    __syncthreads();
    for (int st = 128; st > 0; st >>= 1) {
        if (threadIdx.x < st) sm[threadIdx.x] += sm[threadIdx.x + st];
        __syncthreads();
    }
    if (threadIdx.x == 0) pool[bc] = sm[0] * (1.f / (HH * WW));
}

// ---------------------------------------------------------------------------
// Routing: sigmoid(pooled @ wr.T + br) -> [B,E]
// ---------------------------------------------------------------------------
__global__ void routing_kernel(const float* __restrict__ pool,
                               const float* __restrict__ wr,
                               const float* __restrict__ br,
                               float* __restrict__ rout)
{
    int t = threadIdx.x;
    if (t >= BB * EE) return;
    int b = t / EE, e = t - b * EE;
    float s = br[e];
    for (int c = 0; c < CC; c++) s += pool[b * CC + c] * wr[e * CC + c];
    rout[t] = 1.f / (1.f + __expf(-s));
}

// ---------------------------------------------------------------------------
extern "C" void kernel_launch(void* const* d_in, const int* in_sizes, int n_in,
                              void* d_out, int out_size)
{
    (void)in_sizes; (void)n_in; (void)out_size;
    const float* x   = (const float*)d_in[0];
    const float* w1  = (const float*)d_in[1];
    const float* b1g = (const float*)d_in[2];
    const float* b1b = (const float*)d_in[3];
    const float* b1m = (const float*)d_in[4];
    const float* b1v = (const float*)d_in[5];
    const float* wr  = (const float*)d_in[6];
    const float* br  = (const float*)d_in[7];
    const float* we  = (const float*)d_in[8];
    const float* b2g = (const float*)d_in[9];
    const float* b2b = (const float*)d_in[10];
    const float* b2m = (const float*)d_in[11];
    const float* b2v = (const float*)d_in[12];
    float* out = (float*)d_out;

    float *y, *w1r, *k2, *pool, *rout;
    cudaGetSymbolAddress((void**)&y,    g_y);
    cudaGetSymbolAddress((void**)&w1r,  g_w1r);
    cudaGetSymbolAddress((void**)&k2,   g_k2);
    cudaGetSymbolAddress((void**)&pool, g_pool);
    cudaGetSymbolAddress((void**)&rout, g_rout);

    dim3 cgrid(512, 2);   // 512 pixel tiles (b * 32 row-pairs), 2 cout tiles

    w1_prep<<<256, 256>>>(w1, w1r);
    conv_mma<false, false><<<cgrid, 256>>>(x, w1r, b1g, b1b, b1m, b1v,
                                           nullptr, y);
    pool_kernel<<<BB * CC, 256>>>(y, pool);
    routing_kernel<<<1, 64>>>(pool, wr, br, rout);
    kern_prep<<<dim3(256, BB), 256>>>(rout, we, k2);
    conv_mma<true, true><<<cgrid, 256>>>(y, k2, b2g, b2b, b2m, b2v,
                                         x, out);
}

// round 6
// speedup vs baseline: 2.7415x; 2.6123x over previous
#include <cuda_runtime.h>
#include <cuda_bf16.h>
#include <cstdint>

#define BB 16
#define CC 256
#define HH 64
#define WW 64
#define EE 4
#define EPS_BN 1e-5f
#define NPX (HH*WW)

// smem layout (dynamic): B_h [0,16896) B_l [16896,33792) A bufs [33792, 66560)
#define SM_BL  16896
#define SM_A   33792
#define SM_ABUF 16384
#define SMEMSZ 66560

// gmem scratch (no cudaMalloc -> __device__ globals)
__device__ __align__(16) __nv_bfloat16 g_xh[(size_t)BB*NPX*CC];
__device__ __align__(16) __nv_bfloat16 g_xl[(size_t)BB*NPX*CC];
__device__ __align__(16) __nv_bfloat16 g_yh[(size_t)BB*NPX*CC];
__device__ __align__(16) __nv_bfloat16 g_yl[(size_t)BB*NPX*CC];
__device__ __align__(16) unsigned short g_w1h[(size_t)9*8*CC*32];
__device__ __align__(16) unsigned short g_w1l[(size_t)9*8*CC*32];
__device__ __align__(16) unsigned short g_k2h[(size_t)BB*9*8*CC*32];
__device__ __align__(16) unsigned short g_k2l[(size_t)BB*9*8*CC*32];
__device__ float g_pp[BB*8*CC];
__device__ float g_pool[BB*CC];
__device__ float g_rout[BB*EE];

// ---------------------------------------------------------------------------
__device__ __forceinline__ void bsplit(float v, unsigned short& h, unsigned short& l) {
    __nv_bfloat16 bh = __float2bfloat16(v);
    float r = v - __bfloat162float(bh);
    __nv_bfloat16 bl = __float2bfloat16(r);
    h = *reinterpret_cast<unsigned short*>(&bh);
    l = *reinterpret_cast<unsigned short*>(&bl);
}
__device__ __forceinline__ void cpa16(unsigned dst, const void* src, unsigned sz) {
    asm volatile("cp.async.ca.shared.global [%0], [%1], 16, %2;"
                 :: "r"(dst), "l"(src), "r"(sz));
}
__device__ __forceinline__ void cpa_commit() {
    asm volatile("cp.async.commit_group;");
}
template<int N> __device__ __forceinline__ void cpa_wait() {
    asm volatile("cp.async.wait_group %0;" :: "n"(N));
}
__device__ __forceinline__ void ldm_x4(unsigned& a0, unsigned& a1, unsigned& a2,
                                       unsigned& a3, unsigned addr) {
    asm volatile("ldmatrix.sync.aligned.m8n8.x4.shared.b16 {%0,%1,%2,%3}, [%4];"
                 : "=r"(a0), "=r"(a1), "=r"(a2), "=r"(a3) : "r"(addr));
}
__device__ __forceinline__ void ldm_x2(unsigned& b0, unsigned& b1, unsigned addr) {
    asm volatile("ldmatrix.sync.aligned.m8n8.x2.shared.b16 {%0,%1}, [%2];"
                 : "=r"(b0), "=r"(b1) : "r"(addr));
}
__device__ __forceinline__ void mma16816(float* c, const unsigned* a, const unsigned* b) {
    asm volatile("mma.sync.aligned.m16n8k16.row.col.f32.bf16.bf16.f32 "
                 "{%0,%1,%2,%3}, {%4,%5,%6,%7}, {%8,%9}, {%0,%1,%2,%3};"
                 : "+f"(c[0]), "+f"(c[1]), "+f"(c[2]), "+f"(c[3])
                 : "r"(a[0]), "r"(a[1]), "r"(a[2]), "r"(a[3]),
                   "r"(b[0]), "r"(b[1]));
}

// ---------------------------------------------------------------------------
// Implicit-GEMM 3x3 conv. CTA: 128 cout x 128 px (2 image rows). 8 warps 2Mx4N.
// B halo staged once per ci-chunk (32); all 9 taps read shifted rows.
// A (weights) cp.async'd from PRE-SWIZZLED hi/lo images (linear copy here,
// swizzle applied at ldmatrix read), double-buffered across taps.
// ---------------------------------------------------------------------------
template<bool PS, bool NHWC_OUT>
__global__ __launch_bounds__(256)
void conv_mma(const __nv_bfloat16* __restrict__ actH,
              const __nv_bfloat16* __restrict__ actL,
              const unsigned short* __restrict__ AimgH,
              const unsigned short* __restrict__ AimgL,
              const float* __restrict__ bg, const float* __restrict__ bb_,
              const float* __restrict__ bm, const float* __restrict__ bv,
              const float* __restrict__ resid, float* __restrict__ outF,
              __nv_bfloat16* __restrict__ outH, __nv_bfloat16* __restrict__ outL)
{
    extern __shared__ __align__(1024) char sm[];
    const unsigned sb = (unsigned)__cvta_generic_to_shared(sm);

    const int tid = threadIdx.x, lane = tid & 31, w = tid >> 5;
    const int l2 = lane & 15;
    const int warp_m = w & 1, warp_n = w >> 1;
    const int b = blockIdx.x >> 5;
    const int y0img = (blockIdx.x & 31) << 1;
    const int cout0 = blockIdx.y << 7;

    float c[4][4][4];
    #pragma unroll
    for (int i = 0; i < 4; i++)
        #pragma unroll
        for (int j = 0; j < 4; j++)
            #pragma unroll
            for (int k = 0; k < 4; k++) c[i][j][k] = 0.f;

    for (int ch = 0; ch < 8; ch++) {
        const int ci0 = ch << 5;
        // ---- stage B halo (hi+lo): 264 px x 4 segs x 2 halves = 2112 copies ----
        #pragma unroll
        for (int i = 0; i < 9; i++) {
            int cid = tid + i * 256;
            if (cid < 2112) {
                int half = cid >= 1056;
                int c2 = half ? cid - 1056 : cid;
                int p = c2 >> 2, seg = c2 & 3;
                int hh = p / 66, xi = p - hh * 66;
                int iy = y0img - 1 + hh, ix = xi - 1;
                bool ok = ((unsigned)iy < (unsigned)HH) & ((unsigned)ix < (unsigned)WW);
                const __nv_bfloat16* bas = half ? actL : actH;
                const char* src = ok
                    ? (const char*)(bas + ((size_t)(b * NPX + iy * WW + ix)) * CC + ci0) + seg * 16
                    : (const char*)bas;
                unsigned dst = sb + half * SM_BL + p * 64
                             + (((unsigned)seg << 4) ^ ((((unsigned)p >> 1) & 3u) << 4));
                cpa16(dst, src, ok ? 16u : 0u);
            }
        }
        // ---- stage A for tap 0 (linear copy of pre-swizzled image) ----
        {
            size_t base = (PS ? (size_t)b * 9 * 8 * CC * 32 : 0)
                        + ((size_t)(0 * 8 + ch) * CC + cout0) * 32;
            #pragma unroll
            for (int i = 0; i < 4; i++) {
                int cid = tid + i * 256;
                int half = cid >= 512;
                int c2 = cid & 511;
                int row = c2 >> 2, seg = c2 & 3;
                const unsigned short* img = half ? AimgL : AimgH;
                const char* src = (const char*)(img + base + (size_t)row * 32) + seg * 16;
                unsigned dst = sb + SM_A + half * 8192 + (unsigned)(row * 64 + seg * 16);
                cpa16(dst, src, 16u);
            }
        }
        cpa_commit();

        for (int tap = 0; tap < 9; tap++) {
            if (tap < 8) {
                int bufi = (tap + 1) & 1;
                size_t base = (PS ? (size_t)b * 9 * 8 * CC * 32 : 0)
                            + ((size_t)((tap + 1) * 8 + ch) * CC + cout0) * 32;
                #pragma unroll
                for (int i = 0; i < 4; i++) {
                    int cid = tid + i * 256;
                    int half = cid >= 512;
                    int c2 = cid & 511;
                    int row = c2 >> 2, seg = c2 & 3;
                    const unsigned short* img = half ? AimgL : AimgH;
                    const char* src = (const char*)(img + base + (size_t)row * 32) + seg * 16;
                    unsigned dst = sb + SM_A + bufi * SM_ABUF + half * 8192
                                 + (unsigned)(row * 64 + seg * 16);
                    cpa16(dst, src, 16u);
                }
                cpa_commit();
                cpa_wait<1>();
            } else {
                cpa_wait<0>();
            }
            __syncthreads();

            // ---- compute tap ----
            {
                const int ky = tap / 3 - 1, kx = tap % 3 - 1;
                const unsigned abase = sb + SM_A + (tap & 1) * SM_ABUF;
                #pragma unroll
                for (int ks = 0; ks < 2; ks++) {
                    unsigned bh[4][2], bl[4][2];
                    #pragma unroll
                    for (int ni = 0; ni < 4; ni++) {
                        int n0 = warp_n * 32 + ni * 8;
                        int hh = (n0 >> 6) + ky + 1;
                        int xi = (n0 & 63) + (l2 & 7) + kx + 1;
                        int p = hh * 66 + xi;
                        unsigned kb = ks * 32 + ((l2 >> 3) << 4);
                        unsigned off = p * 64 + (kb ^ ((((unsigned)p >> 1) & 3u) << 4));
                        ldm_x2(bh[ni][0], bh[ni][1], sb + off);
                        ldm_x2(bl[ni][0], bl[ni][1], sb + SM_BL + off);
                    }
                    #pragma unroll
                    for (int mi = 0; mi < 4; mi++) {
                        int row = warp_m * 64 + mi * 16 + l2;
                        unsigned kb2 = ks * 32 + ((lane >> 4) << 4);
                        unsigned offa = row * 64 + (kb2 ^ ((((unsigned)row >> 1) & 3u) << 4));
                        unsigned ah[4], al[4];
                        ldm_x4(ah[0], ah[1], ah[2], ah[3], abase + offa);
                        ldm_x4(al[0], al[1], al[2], al[3], abase + 8192 + offa);
                        #pragma unroll
                        for (int ni = 0; ni < 4; ni++) {
                            mma16816(c[mi][ni], ah, bh[ni]);
                            mma16816(c[mi][ni], ah, bl[ni]);
                            mma16816(c[mi][ni], al, bh[ni]);
                        }
                    }
                }
            }
            __syncthreads();
        }
    }

    // ---- epilogue ----
    const int q = lane & 3, r = lane >> 2;
    if (NHWC_OUT) {
        // BN + SiLU, split to hi/lo, smem transpose to pixel-major, coalesced out
        unsigned short* s16 = (unsigned short*)sm;
        #pragma unroll
        for (int mi = 0; mi < 4; mi++)
            #pragma unroll
            for (int rr = 0; rr < 2; rr++) {
                int cl = warp_m * 64 + mi * 16 + r + rr * 8;
                int cout = cout0 + cl;
                float scale = bg[cout] * rsqrtf(bv[cout] + EPS_BN);
                float shift = bb_[cout] - bm[cout] * scale;
                #pragma unroll
                for (int ni = 0; ni < 4; ni++) {
                    int px = warp_n * 32 + ni * 8 + q * 2;
                    #pragma unroll
                    for (int dx = 0; dx < 2; dx++) {
                        float t = c[mi][ni][rr * 2 + dx] * scale + shift;
                        float o = t / (1.f + __expf(-t));
                        unsigned short h, l;
                        bsplit(o, h, l);
                        s16[(px + dx) * 128 + cl] = h;
                        s16[16384 + (px + dx) * 128 + cl] = l;
                    }
                }
            }
        __syncthreads();
        #pragma unroll
        for (int i = 0; i < 8; i++) {
            int off = (tid + i * 256) * 16;
            int px = off >> 8, inner = off & 255;
            int gpx = (y0img + (px >> 6)) * 64 + (px & 63);
            size_t gb = ((size_t)(b * NPX + gpx) * CC + cout0) * 2 + inner;
            *(uint4*)((char*)outH + gb) = *(uint4*)(sm + off);
            *(uint4*)((char*)outL + gb) = *(uint4*)(sm + 32768 + off);
        }
    } else {
        // BN + SiLU + residual, NCHW float2 stores
        #pragma unroll
        for (int mi = 0; mi < 4; mi++)
            #pragma unroll
            for (int rr = 0; rr < 2; rr++) {
                int cout = cout0 + warp_m * 64 + mi * 16 + r + rr * 8;
                float scale = bg[cout] * rsqrtf(bv[cout] + EPS_BN);
                float shift = bb_[cout] - bm[cout] * scale;
                #pragma unroll
                for (int ni = 0; ni < 4; ni++) {
                    int px = warp_n * 32 + ni * 8 + q * 2;
                    int yy = y0img + (px >> 6), xx = px & 63;
                    size_t oidx = (((size_t)b * CC + cout) * HH + yy) * WW + xx;
                    float t0 = c[mi][ni][rr * 2 + 0] * scale + shift;
                    float t1 = c[mi][ni][rr * 2 + 1] * scale + shift;
                    float o0 = t0 / (1.f + __expf(-t0));
                    float o1 = t1 / (1.f + __expf(-t1));
                    float2 rv = *reinterpret_cast<const float2*>(resid + oidx);
                    float2 ov = {o0 + rv.x, o1 + rv.y};
                    *reinterpret_cast<float2*>(outF + oidx) = ov;
                }
            }
    }
}

// ---------------------------------------------------------------------------
// x: fp32 NCHW -> bf16 hi/lo NHWC
// ---------------------------------------------------------------------------
__global__ void x_prep(const float* __restrict__ x,
                       __nv_bfloat16* __restrict__ xh, __nv_bfloat16* __restrict__ xl)
{
    __shared__ float s[64][65];
    int b = blockIdx.x >> 6, y = blockIdx.x & 63;
    int tid = threadIdx.x;
    for (int cc0 = 0; cc0 < CC; cc0 += 64) {
        __syncthreads();
        #pragma unroll
        for (int i = 0; i < 16; i++) {
            int idx = tid + i * 256;
            int cil = idx >> 6, xx = idx & 63;
            s[cil][xx] = x[(((size_t)b * CC + cc0 + cil) * HH + y) * WW + xx];
        }
        __syncthreads();
        #pragma unroll
        for (int i = 0; i < 16; i++) {
            int idx = tid + i * 256;
            int xx = idx >> 6, cil = idx & 63;
            unsigned short h, l;
            bsplit(s[cil][xx], h, l);
            size_t o = ((size_t)(b * NPX + y * WW + xx)) * CC + cc0 + cil;
            *reinterpret_cast<unsigned short*>(&xh[o]) = h;
            *reinterpret_cast<unsigned short*>(&xl[o]) = l;
        }
    }
}

// ---------------------------------------------------------------------------
// w1: [cout][ci][9] fp32 -> pre-swizzled hi/lo images [tap][chunk][cout][32]
// ---------------------------------------------------------------------------
__global__ void w1_prep(const float* __restrict__ w1,
                        unsigned short* __restrict__ oh, unsigned short* __restrict__ ol)
{
    int cout = blockIdx.x, ci = threadIdx.x;
    const float* p = w1 + ((size_t)cout * CC + ci) * 9;
    int chunk = ci >> 5;
    int swp = (ci & 31) ^ (((cout >> 1) & 3) << 3);
    #pragma unroll
    for (int k = 0; k < 9; k++) {
        unsigned short h, l;
        bsplit(p[k], h, l);
        size_t o = ((size_t)(k * 8 + chunk) * CC + cout) * 32 + swp;
        oh[o] = h;
        ol[o] = l;
    }
}

// ---------------------------------------------------------------------------
// expert mix + reorder: per-sample conv2 weights, pre-swizzled hi/lo images
// ---------------------------------------------------------------------------
__global__ void kern_prep(const float* __restrict__ rout, const float* __restrict__ we,
                          unsigned short* __restrict__ oh, unsigned short* __restrict__ ol)
{
    int cout = blockIdx.x, b = blockIdx.y, ci = threadIdx.x;
    float r0 = rout[b * EE + 0], r1 = rout[b * EE + 1];
    float r2 = rout[b * EE + 2], r3 = rout[b * EE + 3];
    const size_t es = (size_t)CC * CC * 9;
    const float* p = we + ((size_t)cout * CC + ci) * 9;
    int chunk = ci >> 5;
    int swp = (ci & 31) ^ (((cout >> 1) & 3) << 3);
    size_t ob = (size_t)b * 9 * 8 * CC * 32;
    #pragma unroll
    for (int k = 0; k < 9; k++) {
        float m = r0 * p[k] + r1 * p[es + k] + r2 * p[2 * es + k] + r3 * p[3 * es + k];
        unsigned short h, l;
        bsplit(m, h, l);
        size_t o = ob + ((size_t)(k * 8 + chunk) * CC + cout) * 32 + swp;
        oh[o] = h;
        ol[o] = l;
    }
}

// ---------------------------------------------------------------------------
__global__ void pool_partial(const __nv_bfloat16* __restrict__ yh,
                             const __nv_bfloat16* __restrict__ yl,
                             float* __restrict__ pp)
{
    int ch = blockIdx.x, b = blockIdx.y, ci = threadIdx.x;
    size_t base = ((size_t)b * NPX + ch * 512) * CC + ci;
    float s = 0.f;
    for (int p = 0; p < 512; p++)
        s += __bfloat162float(yh[base + (size_t)p * CC]) +
             __bfloat162float(yl[base + (size_t)p * CC]);
    pp[(b * 8 + ch) * CC + ci] = s;
}

__global__ void pool_final(const float* __restrict__ pp, float* __restrict__ pool)
{
    int b = blockIdx.x, ci = threadIdx.x;
    float s = 0.f;
    #pragma unroll
    for (int ch = 0; ch < 8; ch++) s += pp[(b * 8 + ch) * CC + ci];
    pool[b * CC + ci] = s * (1.f / NPX);
}

__global__ void routing_kernel(const float* __restrict__ pool, const float* __restrict__ wr,
                               const float* __restrict__ br, float* __restrict__ rout)
{
    int b = blockIdx.x;
    int e = threadIdx.x >> 5, lane = threadIdx.x & 31;
    float s = 0.f;
    for (int cx = lane; cx < CC; cx += 32) s += pool[b * CC + cx] * wr[e * CC + cx];
    #pragma unroll
    for (int o = 16; o; o >>= 1) s += __shfl_xor_sync(0xffffffffu, s, o);
    if (lane == 0) rout[b * EE + e] = 1.f / (1.f + __expf(-(s + br[e])));
}

// ---------------------------------------------------------------------------
extern "C" void kernel_launch(void* const* d_in, const int* in_sizes, int n_in,
                              void* d_out, int out_size)
{
    (void)in_sizes; (void)n_in; (void)out_size;
    const float* x   = (const float*)d_in[0];
    const float* w1  = (const float*)d_in[1];
    const float* b1g = (const float*)d_in[2];
    const float* b1b = (const float*)d_in[3];
    const float* b1m = (const float*)d_in[4];
    const float* b1v = (const float*)d_in[5];
    const float* wr  = (const float*)d_in[6];
    const float* br  = (const float*)d_in[7];
    const float* we  = (const float*)d_in[8];
    const float* b2g = (const float*)d_in[9];
    const float* b2b = (const float*)d_in[10];
    const float* b2m = (const float*)d_in[11];
    const float* b2v = (const float*)d_in[12];
    float* out = (float*)d_out;

    __nv_bfloat16 *xh, *xl, *yh, *yl;
    unsigned short *w1h, *w1l, *k2h, *k2l;
    float *pp, *pool, *rout;
    cudaGetSymbolAddress((void**)&xh,  g_xh);
    cudaGetSymbolAddress((void**)&xl,  g_xl);
    cudaGetSymbolAddress((void**)&yh,  g_yh);
    cudaGetSymbolAddress((void**)&yl,  g_yl);
    cudaGetSymbolAddress((void**)&w1h, g_w1h);
    cudaGetSymbolAddress((void**)&w1l, g_w1l);
    cudaGetSymbolAddress((void**)&k2h, g_k2h);
    cudaGetSymbolAddress((void**)&k2l, g_k2l);
    cudaGetSymbolAddress((void**)&pp,   g_pp);
    cudaGetSymbolAddress((void**)&pool, g_pool);
    cudaGetSymbolAddress((void**)&rout, g_rout);

    cudaFuncSetAttribute(conv_mma<false, true>,
                         cudaFuncAttributeMaxDynamicSharedMemorySize, SMEMSZ);
    cudaFuncSetAttribute(conv_mma<true, false>,
                         cudaFuncAttributeMaxDynamicSharedMemorySize, SMEMSZ);

    dim3 cgrid(512, 2);

    x_prep<<<1024, 256>>>(x, xh, xl);
    w1_prep<<<256, 256>>>(w1, w1h, w1l);
    conv_mma<false, true><<<cgrid, 256, SMEMSZ>>>(
        xh, xl, w1h, w1l, b1g, b1b, b1m, b1v, nullptr, nullptr, yh, yl);
    pool_partial<<<dim3(8, BB), 256>>>(yh, yl, pp);
    pool_final<<<BB, 256>>>(pp, pool);
    routing_kernel<<<BB, 128>>>(pool, wr, br, rout);
    kern_prep<<<dim3(256, BB), 256>>>(rout, we, k2h, k2l);
    conv_mma<true, false><<<cgrid, 256, SMEMSZ>>>(
        yh, yl, k2h, k2l, b2g, b2b, b2m, b2v, x, out, nullptr, nullptr);
}

// round 7
// speedup vs baseline: 2.7894x; 1.0175x over previous
#include <cuda_runtime.h>
#include <cuda_bf16.h>
#include <cstdint>

#define BB 16
#define CC 256
#define HH 64
#define WW 64
#define EE 4
#define EPS_BN 1e-5f
#define NPX (HH*WW)

// smem layout (dynamic): B_h [0,16896) B_l [16896,33792) A bufs [33792, 66560)
// epilogue reuse: transpose s16 [0,65536), pool partials [65536,67584)
#define SM_BL  16896
#define SM_A   33792
#define SM_ABUF 16384
#define SMEMSZ 67584

// gmem scratch (no cudaMalloc -> __device__ globals)
__device__ __align__(16) __nv_bfloat16 g_xh[(size_t)BB*NPX*CC];
__device__ __align__(16) __nv_bfloat16 g_xl[(size_t)BB*NPX*CC];
__device__ __align__(16) __nv_bfloat16 g_yh[(size_t)BB*NPX*CC];
__device__ __align__(16) __nv_bfloat16 g_yl[(size_t)BB*NPX*CC];
__device__ __align__(16) unsigned short g_w1h[(size_t)9*8*CC*32];
__device__ __align__(16) unsigned short g_w1l[(size_t)9*8*CC*32];
__device__ __align__(16) unsigned short g_k2h[(size_t)BB*9*8*CC*32];
__device__ __align__(16) unsigned short g_k2l[(size_t)BB*9*8*CC*32];
__device__ float g_pp[(size_t)BB*32*CC];
__device__ float g_pool[BB*CC];
__device__ float g_rout[BB*EE];

// ---------------------------------------------------------------------------
__device__ __forceinline__ void bsplit(float v, unsigned short& h, unsigned short& l) {
    __nv_bfloat16 bh = __float2bfloat16(v);
    float r = v - __bfloat162float(bh);
    __nv_bfloat16 bl = __float2bfloat16(r);
    h = *reinterpret_cast<unsigned short*>(&bh);
    l = *reinterpret_cast<unsigned short*>(&bl);
}
__device__ __forceinline__ void cpa16(unsigned dst, const void* src, unsigned sz) {
    asm volatile("cp.async.ca.shared.global [%0], [%1], 16, %2;"
                 :: "r"(dst), "l"(src), "r"(sz));
}
__device__ __forceinline__ void cpa_commit() {
    asm volatile("cp.async.commit_group;");
}
template<int N> __device__ __forceinline__ void cpa_wait() {
    asm volatile("cp.async.wait_group %0;" :: "n"(N));
}
__device__ __forceinline__ void ldm_x4(unsigned& a0, unsigned& a1, unsigned& a2,
                                       unsigned& a3, unsigned addr) {
    asm volatile("ldmatrix.sync.aligned.m8n8.x4.shared.b16 {%0,%1,%2,%3}, [%4];"
                 : "=r"(a0), "=r"(a1), "=r"(a2), "=r"(a3) : "r"(addr));
}
__device__ __forceinline__ void ldm_x2(unsigned& b0, unsigned& b1, unsigned addr) {
    asm volatile("ldmatrix.sync.aligned.m8n8.x2.shared.b16 {%0,%1}, [%2];"
                 : "=r"(b0), "=r"(b1) : "r"(addr));
}
__device__ __forceinline__ void mma16816(float* c, const unsigned* a, const unsigned* b) {
    asm volatile("mma.sync.aligned.m16n8k16.row.col.f32.bf16.bf16.f32 "
                 "{%0,%1,%2,%3}, {%4,%5,%6,%7}, {%8,%9}, {%0,%1,%2,%3};"
                 : "+f"(c[0]), "+f"(c[1]), "+f"(c[2]), "+f"(c[3])
                 : "r"(a[0]), "r"(a[1]), "r"(a[2]), "r"(a[3]),
                   "r"(b[0]), "r"(b[1]));
}

// ---------------------------------------------------------------------------
// Implicit-GEMM 3x3 conv. CTA: 128 cout x 128 px (2 image rows). 8 warps 2Mx4N.
// B halo staged once per ci-chunk (32); all 9 taps read shifted rows.
// A (weights) cp.async'd from PRE-SWIZZLED hi/lo images, double-buffered.
// ONE barrier per tap: stage(t+1) after sync(t) is hazard-free (other buffer,
// last read by compute(t-1) which sync(t) has ordered).
// ---------------------------------------------------------------------------
template<bool PS, bool NHWC_OUT>
__global__ __launch_bounds__(256)
void conv_mma(const __nv_bfloat16* __restrict__ actH,
              const __nv_bfloat16* __restrict__ actL,
              const unsigned short* __restrict__ AimgH,
              const unsigned short* __restrict__ AimgL,
              const float* __restrict__ bg, const float* __restrict__ bb_,
              const float* __restrict__ bm, const float* __restrict__ bv,
              const float* __restrict__ resid, float* __restrict__ outF,
              __nv_bfloat16* __restrict__ outH, __nv_bfloat16* __restrict__ outL,
              float* __restrict__ pp)
{
    extern __shared__ __align__(1024) char sm[];
    const unsigned sb = (unsigned)__cvta_generic_to_shared(sm);

    const int tid = threadIdx.x, lane = tid & 31, w = tid >> 5;
    const int l2 = lane & 15;
    const int warp_m = w & 1, warp_n = w >> 1;
    const int b = blockIdx.x >> 5;
    const int y0img = (blockIdx.x & 31) << 1;
    const int cout0 = blockIdx.y << 7;

    float c[4][4][4];
    #pragma unroll
    for (int i = 0; i < 4; i++)
        #pragma unroll
        for (int j = 0; j < 4; j++)
            #pragma unroll
            for (int k = 0; k < 4; k++) c[i][j][k] = 0.f;

    for (int ch = 0; ch < 8; ch++) {
        const int ci0 = ch << 5;
        __syncthreads();   // all warps done with prev chunk's B and buf0
        // ---- stage B halo (hi+lo): 264 px x 4 segs x 2 halves = 2112 copies ----
        #pragma unroll
        for (int i = 0; i < 9; i++) {
            int cid = tid + i * 256;
            if (cid < 2112) {
                int half = cid >= 1056;
                int c2 = half ? cid - 1056 : cid;
                int p = c2 >> 2, seg = c2 & 3;
                int hh = p / 66, xi = p - hh * 66;
                int iy = y0img - 1 + hh, ix = xi - 1;
                bool ok = ((unsigned)iy < (unsigned)HH) & ((unsigned)ix < (unsigned)WW);
                const __nv_bfloat16* bas = half ? actL : actH;
                const char* src = ok
                    ? (const char*)(bas + ((size_t)(b * NPX + iy * WW + ix)) * CC + ci0) + seg * 16
                    : (const char*)bas;
                unsigned dst = sb + half * SM_BL + p * 64
                             + (((unsigned)seg << 4) ^ ((((unsigned)p >> 1) & 3u) << 4));
                cpa16(dst, src, ok ? 16u : 0u);
            }
        }
        // ---- stage A for tap 0 (linear copy of pre-swizzled image) ----
        {
            size_t base = (PS ? (size_t)b * 9 * 8 * CC * 32 : 0)
                        + ((size_t)(0 * 8 + ch) * CC + cout0) * 32;
            #pragma unroll
            for (int i = 0; i < 4; i++) {
                int cid = tid + i * 256;
                int half = cid >= 512;
                int c2 = cid & 511;
                int row = c2 >> 2, seg = c2 & 3;
                const unsigned short* img = half ? AimgL : AimgH;
                const char* src = (const char*)(img + base + (size_t)row * 32) + seg * 16;
                unsigned dst = sb + SM_A + half * 8192 + (unsigned)(row * 64 + seg * 16);
                cpa16(dst, src, 16u);
            }
        }
        cpa_commit();

        for (int tap = 0; tap < 9; tap++) {
            cpa_wait<0>();
            __syncthreads();   // tap data visible to all; all warps past compute(tap-1)

            if (tap < 8) {
                int bufi = (tap + 1) & 1;
                size_t base = (PS ? (size_t)b * 9 * 8 * CC * 32 : 0)
                            + ((size_t)((tap + 1) * 8 + ch) * CC + cout0) * 32;
                #pragma unroll
                for (int i = 0; i < 4; i++) {
                    int cid = tid + i * 256;
                    int half = cid >= 512;
                    int c2 = cid & 511;
                    int row = c2 >> 2, seg = c2 & 3;
                    const unsigned short* img = half ? AimgL : AimgH;
                    const char* src = (const char*)(img + base + (size_t)row * 32) + seg * 16;
                    unsigned dst = sb + SM_A + bufi * SM_ABUF + half * 8192
                                 + (unsigned)(row * 64 + seg * 16);
                    cpa16(dst, src, 16u);
                }
                cpa_commit();
            }

            // ---- compute tap ----
            {
                const int ky = tap / 3 - 1, kx = tap % 3 - 1;
                const unsigned abase = sb + SM_A + (tap & 1) * SM_ABUF;
                #pragma unroll
                for (int ks = 0; ks < 2; ks++) {
                    unsigned bh[4][2], bl[4][2];
                    #pragma unroll
                    for (int ni = 0; ni < 4; ni++) {
                        int n0 = warp_n * 32 + ni * 8;
                        int hh = (n0 >> 6) + ky + 1;
                        int xi = (n0 & 63) + (l2 & 7) + kx + 1;
                        int p = hh * 66 + xi;
                        unsigned kb = ks * 32 + ((l2 >> 3) << 4);
                        unsigned off = p * 64 + (kb ^ ((((unsigned)p >> 1) & 3u) << 4));
                        ldm_x2(bh[ni][0], bh[ni][1], sb + off);
                        ldm_x2(bl[ni][0], bl[ni][1], sb + SM_BL + off);
                    }
                    #pragma unroll
                    for (int mi = 0; mi < 4; mi++) {
                        int row = warp_m * 64 + mi * 16 + l2;
                        unsigned kb2 = ks * 32 + ((lane >> 4) << 4);
                        unsigned offa = row * 64 + (kb2 ^ ((((unsigned)row >> 1) & 3u) << 4));
                        unsigned ah[4], al[4];
                        ldm_x4(ah[0], ah[1], ah[2], ah[3], abase + offa);
                        ldm_x4(al[0], al[1], al[2], al[3], abase + 8192 + offa);
                        #pragma unroll
                        for (int ni = 0; ni < 4; ni++) {
                            mma16816(c[mi][ni], ah, bh[ni]);
                            mma16816(c[mi][ni], ah, bl[ni]);
                            mma16816(c[mi][ni], al, bh[ni]);
                        }
                    }
                }
            }
        }
    }

    // ---- epilogue ----
    const int q = lane & 3, r = lane >> 2;
    if (NHWC_OUT) {
        __syncthreads();   // smem (B/A) dead before reuse as transpose buffer
        float psum[4][2] = {{0.f, 0.f}, {0.f, 0.f}, {0.f, 0.f}, {0.f, 0.f}};
        unsigned short* s16 = (unsigned short*)sm;
        #pragma unroll
        for (int mi = 0; mi < 4; mi++)
            #pragma unroll
            for (int rr = 0; rr < 2; rr++) {
                int cl = warp_m * 64 + mi * 16 + r + rr * 8;
                int cout = cout0 + cl;
                float scale = bg[cout] * rsqrtf(bv[cout] + EPS_BN);
                float shift = bb_[cout] - bm[cout] * scale;
                #pragma unroll
                for (int ni = 0; ni < 4; ni++) {
                    int px = warp_n * 32 + ni * 8 + q * 2;
                    #pragma unroll
                    for (int dx = 0; dx < 2; dx++) {
                        float t = c[mi][ni][rr * 2 + dx] * scale + shift;
                        float o = t / (1.f + __expf(-t));
                        psum[mi][rr] += o;
                        unsigned short h, l;
                        bsplit(o, h, l);
                        s16[(px + dx) * 128 + cl] = h;
                        s16[16384 + (px + dx) * 128 + cl] = l;
                    }
                }
            }
        __syncthreads();
        #pragma unroll
        for (int i = 0; i < 8; i++) {
            int off = (tid + i * 256) * 16;
            int px = off >> 8, inner = off & 255;
            int gpx = (y0img + (px >> 6)) * 64 + (px & 63);
            size_t gb = ((size_t)(b * NPX + gpx) * CC + cout0) * 2 + inner;
            *(uint4*)((char*)outH + gb) = *(uint4*)(sm + off);
            *(uint4*)((char*)outL + gb) = *(uint4*)(sm + 32768 + off);
        }
        // ---- fused pool partials (deterministic, no atomics) ----
        float* s_pool = (float*)(sm + 65536);
        #pragma unroll
        for (int mi = 0; mi < 4; mi++)
            #pragma unroll
            for (int rr = 0; rr < 2; rr++) {
                float v = psum[mi][rr];
                v += __shfl_xor_sync(0xffffffffu, v, 1);
                v += __shfl_xor_sync(0xffffffffu, v, 2);
                if (q == 0)
                    s_pool[warp_n * 128 + warp_m * 64 + mi * 16 + r + rr * 8] = v;
            }
        __syncthreads();
        if (tid < 128) {
            float s = s_pool[tid] + s_pool[128 + tid] + s_pool[256 + tid] + s_pool[384 + tid];
            pp[((size_t)(b * 32 + (blockIdx.x & 31))) * CC + cout0 + tid] = s * (1.f / NPX);
        }
    } else {
        // BN + SiLU + residual, NCHW float2 stores
        #pragma unroll
        for (int mi = 0; mi < 4; mi++)
            #pragma unroll
            for (int rr = 0; rr < 2; rr++) {
                int cout = cout0 + warp_m * 64 + mi * 16 + r + rr * 8;
                float scale = bg[cout] * rsqrtf(bv[cout] + EPS_BN);
                float shift = bb_[cout] - bm[cout] * scale;
                #pragma unroll
                for (int ni = 0; ni < 4; ni++) {
                    int px = warp_n * 32 + ni * 8 + q * 2;
                    int yy = y0img + (px >> 6), xx = px & 63;
                    size_t oidx = (((size_t)b * CC + cout) * HH + yy) * WW + xx;
                    float t0 = c[mi][ni][rr * 2 + 0] * scale + shift;
                    float t1 = c[mi][ni][rr * 2 + 1] * scale + shift;
                    float o0 = t0 / (1.f + __expf(-t0));
                    float o1 = t1 / (1.f + __expf(-t1));
                    float2 rv = *reinterpret_cast<const float2*>(resid + oidx);
                    float2 ov = {o0 + rv.x, o1 + rv.y};
                    *reinterpret_cast<float2*>(outF + oidx) = ov;
                }
            }
    }
}

// ---------------------------------------------------------------------------
// x: fp32 NCHW -> bf16 hi/lo NHWC
// ---------------------------------------------------------------------------
__global__ void x_prep(const float* __restrict__ x,
                       __nv_bfloat16* __restrict__ xh, __nv_bfloat16* __restrict__ xl)
{
    __shared__ float s[64][65];
    int b = blockIdx.x >> 6, y = blockIdx.x & 63;
    int tid = threadIdx.x;
    for (int cc0 = 0; cc0 < CC; cc0 += 64) {
        __syncthreads();
        #pragma unroll
        for (int i = 0; i < 16; i++) {
            int idx = tid + i * 256;
            int cil = idx >> 6, xx = idx & 63;
            s[cil][xx] = x[(((size_t)b * CC + cc0 + cil) * HH + y) * WW + xx];
        }
        __syncthreads();
        #pragma unroll
        for (int i = 0; i < 16; i++) {
            int idx = tid + i * 256;
            int xx = idx >> 6, cil = idx & 63;
            unsigned short h, l;
            bsplit(s[cil][xx], h, l);
            size_t o = ((size_t)(b * NPX + y * WW + xx)) * CC + cc0 + cil;
            *reinterpret_cast<unsigned short*>(&xh[o]) = h;
            *reinterpret_cast<unsigned short*>(&xl[o]) = l;
        }
    }
}

// ---------------------------------------------------------------------------
// w1: coalesced read into smem, then swizzled-image writes
// out layout: [tap*8+chunk][cout][32] with ci-halves XOR'd by (cout>>1)&3
// ---------------------------------------------------------------------------
__global__ void w1_prep(const float* __restrict__ w1,
                        unsigned short* __restrict__ oh, unsigned short* __restrict__ ol)
{
    __shared__ float raw[2304];
    int cout = blockIdx.x, tid = threadIdx.x;
    for (int i = tid; i < 2304; i += 256) raw[i] = w1[(size_t)cout * 2304 + i];
    __syncthreads();
    int xr = ((cout >> 1) & 3) << 3;
    for (int j = tid; j < 2304; j += 256) {
        int row = j >> 5, pos = j & 31;       // row = k*8+chunk
        int k = row >> 3, chunk = row & 7;
        int ci = chunk * 32 + (pos ^ xr);
        unsigned short h, l;
        bsplit(raw[ci * 9 + k], h, l);
        size_t o = ((size_t)row * CC + cout) * 32 + pos;
        oh[o] = h;
        ol[o] = l;
    }
}

// ---------------------------------------------------------------------------
// expert mix + reorder, one pass: block per cout reads expert rows ONCE
// (coalesced), mixes all 16 samples from smem.
// ---------------------------------------------------------------------------
__global__ void kern_prep(const float* __restrict__ rout, const float* __restrict__ we,
                          unsigned short* __restrict__ oh, unsigned short* __restrict__ ol)
{
    __shared__ float raw[EE][2304];
    __shared__ float mix[2304];
    int cout = blockIdx.x, tid = threadIdx.x;
    const size_t es = (size_t)CC * CC * 9;
    #pragma unroll
    for (int e = 0; e < EE; e++)
        for (int i = tid; i < 2304; i += 256)
            raw[e][i] = we[e * es + (size_t)cout * 2304 + i];
    __syncthreads();
    int xr = ((cout >> 1) & 3) << 3;
    for (int b = 0; b < BB; b++) {
        float r0 = rout[b * EE + 0], r1 = rout[b * EE + 1];
        float r2 = rout[b * EE + 2], r3 = rout[b * EE + 3];
        for (int i = tid; i < 2304; i += 256)
            mix[i] = r0 * raw[0][i] + r1 * raw[1][i] + r2 * raw[2][i] + r3 * raw[3][i];
        __syncthreads();
        size_t ob = (size_t)b * 9 * 8 * CC * 32;
        for (int j = tid; j < 2304; j += 256) {
            int row = j >> 5, pos = j & 31;
            int k = row >> 3, chunk = row & 7;
            int ci = chunk * 32 + (pos ^ xr);
            unsigned short h, l;
            bsplit(mix[ci * 9 + k], h, l);
            size_t o = ob + ((size_t)row * CC + cout) * 32 + pos;
            oh[o] = h;
            ol[o] = l;
        }
        __syncthreads();
    }
}

// ---------------------------------------------------------------------------
__global__ void pool_final(const float* __restrict__ pp, float* __restrict__ pool)
{
    int b = blockIdx.x, ci = threadIdx.x;
    float s = 0.f;
    #pragma unroll
    for (int yt = 0; yt < 32; yt++) s += pp[((size_t)(b * 32 + yt)) * CC + ci];
    pool[b * CC + ci] = s;
}

__global__ void routing_kernel(const float* __restrict__ pool, const float* __restrict__ wr,
                               const float* __restrict__ br, float* __restrict__ rout)
{
    int b = blockIdx.x;
    int e = threadIdx.x >> 5, lane = threadIdx.x & 31;
    float s = 0.f;
    for (int cx = lane; cx < CC; cx += 32) s += pool[b * CC + cx] * wr[e * CC + cx];
    #pragma unroll
    for (int o = 16; o; o >>= 1) s += __shfl_xor_sync(0xffffffffu, s, o);
    if (lane == 0) rout[b * EE + e] = 1.f / (1.f + __expf(-(s + br[e])));
}

// ---------------------------------------------------------------------------
extern "C" void kernel_launch(void* const* d_in, const int* in_sizes, int n_in,
                              void* d_out, int out_size)
{
    (void)in_sizes; (void)n_in; (void)out_size;
    const float* x   = (const float*)d_in[0];
    const float* w1  = (const float*)d_in[1];
    const float* b1g = (const float*)d_in[2];
    const float* b1b = (const float*)d_in[3];
    const float* b1m = (const float*)d_in[4];
    const float* b1v = (const float*)d_in[5];
    const float* wr  = (const float*)d_in[6];
    const float* br  = (const float*)d_in[7];
    const float* we  = (const float*)d_in[8];
    const float* b2g = (const float*)d_in[9];
    const float* b2b = (const float*)d_in[10];
    const float* b2m = (const float*)d_in[11];
    const float* b2v = (const float*)d_in[12];
    float* out = (float*)d_out;

    __nv_bfloat16 *xh, *xl, *yh, *yl;
    unsigned short *w1h, *w1l, *k2h, *k2l;
    float *pp, *pool, *rout;
    cudaGetSymbolAddress((void**)&xh,  g_xh);
    cudaGetSymbolAddress((void**)&xl,  g_xl);
    cudaGetSymbolAddress((void**)&yh,  g_yh);
    cudaGetSymbolAddress((void**)&yl,  g_yl);
    cudaGetSymbolAddress((void**)&w1h, g_w1h);
    cudaGetSymbolAddress((void**)&w1l, g_w1l);
    cudaGetSymbolAddress((void**)&k2h, g_k2h);
    cudaGetSymbolAddress((void**)&k2l, g_k2l);
    cudaGetSymbolAddress((void**)&pp,   g_pp);
    cudaGetSymbolAddress((void**)&pool, g_pool);
    cudaGetSymbolAddress((void**)&rout, g_rout);

    cudaFuncSetAttribute(conv_mma<false, true>,
                         cudaFuncAttributeMaxDynamicSharedMemorySize, SMEMSZ);
    cudaFuncSetAttribute(conv_mma<true, false>,
                         cudaFuncAttributeMaxDynamicSharedMemorySize, SMEMSZ);

    dim3 cgrid(512, 2);

    x_prep<<<1024, 256>>>(x, xh, xl);
    w1_prep<<<256, 256>>>(w1, w1h, w1l);
    conv_mma<false, true><<<cgrid, 256, SMEMSZ>>>(
        xh, xl, w1h, w1l, b1g, b1b, b1m, b1v, nullptr, nullptr, yh, yl, pp);
    pool_final<<<BB, 256>>>(pp, pool);
    routing_kernel<<<BB, 128>>>(pool, wr, br, rout);
    kern_prep<<<256, 256>>>(rout, we, k2h, k2l);
    conv_mma<true, false><<<cgrid, 256, SMEMSZ>>>(
        yh, yl, k2h, k2l, b2g, b2b, b2m, b2v, x, out, nullptr, nullptr, nullptr);
}